// round 15
// baseline (speedup 1.0000x reference)
#include <cuda_runtime.h>
#include <math.h>

// Problem constants
#define BB 2048     // batch (samples == queries)
#define RR 64       // receptors
#define TILES 16    // BB / 128
#define NPAIRS 136  // TILES*(TILES+1)/2
#define QT 16       // query tiles for logsum
#define CB 128      // row-chunks for Gram/colsum partials
#define CROWS 16    // rows per chunk (CB*CROWS == BB)
#define GRB 32      // gram-reduce blocks (32 x 128 threads = 4096 cells)

// -------- device scratch (static: no allocations allowed) --------
__device__ float g_act_t[RR * BB];         // column-major transpose of act (unscaled)
__device__ float g_k[RR];                  // invh * sqrt(0.5*log2e) per receptor
__device__ float g_dnorm[RR];              // invh / (B * sqrt(2*pi))
__device__ float g_mean[RR];
__device__ float g_colsum[RR * CB];        // per-chunk column sums, TRANSPOSED [r][chunk]
__device__ float g_colsumsq[RR * CB];      // per-chunk column sums of squares, [r][chunk]
__device__ float g_part[TILES * RR * BB];  // [slot][r][q] density partial sums (8MB)
__device__ float g_gram[CB * RR * RR];     // RAW (uncentered) Gram partials (2MB)
__device__ unsigned int g_sem = 0;         // prep ticket; self-resets to 0 each launch

// Hardware exp2: single MUFU.EX2 (ftz on tiny results — harmless here).
__device__ __forceinline__ float ex2(float x) {
    float y;
    asm("ex2.approx.ftz.f32 %0, %1;" : "=f"(y) : "f"(x));
    return y;
}

// ---------------------------------------------------------------------------
// Stage 1 (now also finalizes stats): per-chunk raw Gram (64x64) + per-chunk
// column sum / sum-of-squares (stored transposed for coalesced re-read) +
// transposed copy of the chunk into g_act_t. The LAST block (128-block
// atomic ticket — cheap at this scale, unlike the failed 1056-block variant)
// re-reads the two 32KB partial arrays as pure float4 streams and computes
// per-receptor mean/var/h/k. Deterministic: fixed addresses, fixed order,
// independent of which block is last; g_sem self-resets for graph replays.
// Block 0 zeroes out[0] (poisoned by the harness) for the reduce-stage
// accumulate combine.
// ---------------------------------------------------------------------------
__global__ void prep_kernel(const float* __restrict__ act, float* __restrict__ out) {
    __shared__ float ch[CROWS * RR];   // 16 x 64 raw rows (4KB)
    __shared__ float fin[512];
    __shared__ unsigned int s_ticket;
    const int b   = blockIdx.x;        // 0..CB-1
    const int tid = threadIdx.x;       // 256

    if (b == 0 && tid == 0) out[0] = 0.f;

    // coalesced float4 load: 256 threads x 1 float4 = 1024 floats
    reinterpret_cast<float4*>(ch)[tid] =
        reinterpret_cast<const float4*>(act + b * CROWS * RR)[tid];
    __syncthreads();

    // transposed write: i = r*16 + s  ->  g_act_t[r*BB + b*16 + s]
    #pragma unroll
    for (int i = tid; i < CROWS * RR; i += 256) {
        const int r = i >> 4;
        const int s = i & 15;
        g_act_t[r * BB + b * CROWS + s] = ch[s * RR + r];
    }

    // per-chunk column sum + sumsq (threads 0..63), stored transposed
    if (tid < RR) {
        float cs = 0.f, cq = 0.f;
        #pragma unroll
        for (int s = 0; s < CROWS; ++s) {
            const float v = ch[s * RR + tid];
            cs += v;
            cq += v * v;
        }
        g_colsum[tid * CB + b]   = cs;
        g_colsumsq[tid * CB + b] = cq;
    }

    const int ti = tid & 15;   // column-group i
    const int tj = tid >> 4;   // column-group j
    float acc[4][4];
    #pragma unroll
    for (int y = 0; y < 4; ++y)
        #pragma unroll
        for (int x = 0; x < 4; ++x) acc[y][x] = 0.f;

    const float4* __restrict__ s4 = reinterpret_cast<const float4*>(ch);
    #pragma unroll
    for (int s = 0; s < CROWS; ++s) {
        const float4 ai = s4[s * 16 + ti];
        const float4 aj = s4[s * 16 + tj];
        const float av[4] = { ai.x, ai.y, ai.z, ai.w };
        const float bv[4] = { aj.x, aj.y, aj.z, aj.w };
        #pragma unroll
        for (int y = 0; y < 4; ++y)
            #pragma unroll
            for (int x = 0; x < 4; ++x)
                acc[y][x] += av[x] * bv[y];
    }

    float* __restrict__ gp = g_gram + b * RR * RR;
    #pragma unroll
    for (int y = 0; y < 4; ++y)
        #pragma unroll
        for (int x = 0; x < 4; ++x)
            gp[(tj * 4 + y) * RR + (ti * 4 + x)] = acc[y][x];

    // ---- last-block stats finalize ----
    __threadfence();                       // release colsum/colsumsq writes
    __syncthreads();
    if (tid == 0) s_ticket = atomicAdd(&g_sem, 1u);
    __syncthreads();
    if (s_ticket != CB - 1) return;

    __threadfence();                       // acquire all blocks' partials

    // 4 threads per receptor, each sums 32 contiguous chunks (8 float4s)
    const int r = tid >> 2;
    const int q = tid & 3;
    const float4* __restrict__ c4 = reinterpret_cast<const float4*>(g_colsum   + r * CB + q * 32);
    const float4* __restrict__ q4 = reinterpret_cast<const float4*>(g_colsumsq + r * CB + q * 32);
    float s = 0.f, ss = 0.f;
    #pragma unroll
    for (int i = 0; i < 8; ++i) {
        const float4 a = c4[i];
        const float4 d = q4[i];
        s  += (a.x + a.y) + (a.z + a.w);
        ss += (d.x + d.y) + (d.z + d.w);
    }
    fin[tid]       = s;
    fin[256 + tid] = ss;
    __syncthreads();
    if (q == 0) {
        const float S  = (fin[tid]       + fin[tid + 1])       + (fin[tid + 2]       + fin[tid + 3]);
        const float SS = (fin[256 + tid] + fin[256 + tid + 1]) + (fin[256 + tid + 2] + fin[256 + tid + 3]);
        const float mean = S * (1.0f / BB);
        const float ssc  = SS - (float)BB * mean * mean;   // raw-moment form, validated
        const float var  = ssc * (1.0f / (BB - 1));
        const float stdv = sqrtf(var);
        // BANDWIDTH_FACTOR * std * B^(-0.2);  2048^(-0.2) = 0.21763764
        const float h    = fmaxf(1.06f * stdv * 0.21763764f, 1e-4f);
        const float invh = 1.0f / h;
        // sqrt(0.5 * log2(e)) so exp(-0.5*u^2) == 2^{-(u')^2}
        g_k[r]     = invh * 0.84932184f;
        g_dnorm[r] = invh * (1.0f / (2048.0f * 2.5066282746310002f));
        g_mean[r]  = mean;
    }
    if (tid == 0) g_sem = 0u;              // self-reset for the next replay
}

// ---------------------------------------------------------------------------
// Stage 2: symmetric KDE from the column-major transpose (coalesced float4
// loads, L2-resident), scaling by g_k[r] inline at load. Block = (tile-pair,
// receptor), 128 threads. Each lane owns 4 tile-J columns in registers;
// (query, row accumulator) rotates across the 32 lanes via SHFL. Off-diag
// pairs: each exp serves both a row (tile-I) and a column (tile-J) density.
// ---------------------------------------------------------------------------
__global__ void kde_sym_kernel() {
    const int r = blockIdx.y;
    // map linear pair index -> (I, J), I <= J
    int I = 0, rem = blockIdx.x;
    while (rem >= TILES - I) { rem -= TILES - I; ++I; }
    const int J = I + rem;

    const int tid  = threadIdx.x;   // 128
    const int lane = tid & 31;
    const int w    = tid >> 5;

    const float kk = g_k[r];
    const float* __restrict__ col = g_act_t + r * BB;

    float4 sv = reinterpret_cast<const float4*>(col + J * 128)[lane];
    sv.x *= kk; sv.y *= kk; sv.z *= kk; sv.w *= kk;
    float aqc  = col[I * 128 + tid] * kk;
    float rowc = 0.f;
    float4 ca  = make_float4(0.f, 0.f, 0.f, 0.f);

    const unsigned FULL = 0xFFFFFFFFu;

    if (I != J) {
        #pragma unroll 8
        for (int m = 0; m < 32; ++m) {
            float u, v0, v1, v2, v3;
            u = aqc - sv.x; v0 = ex2(-u * u);
            u = aqc - sv.y; v1 = ex2(-u * u);
            u = aqc - sv.z; v2 = ex2(-u * u);
            u = aqc - sv.w; v3 = ex2(-u * u);
            ca.x += v0; ca.y += v1; ca.z += v2; ca.w += v3;
            rowc += (v0 + v1) + (v2 + v3);
            aqc  = __shfl_sync(FULL, aqc,  (lane + 1) & 31);
            rowc = __shfl_sync(FULL, rowc, (lane + 1) & 31);
        }

        __shared__ float shc[4][128];
        reinterpret_cast<float4*>(shc[w])[lane] = ca;
        __syncthreads();
        const float ct = shc[0][tid] + shc[1][tid] + shc[2][tid] + shc[3][tid];

        g_part[I * (RR * BB) + r * BB + J * 128 + tid] = ct;    // tile-J densities
        g_part[J * (RR * BB) + r * BB + I * 128 + tid] = rowc;  // tile-I densities
    } else {
        #pragma unroll 8
        for (int m = 0; m < 32; ++m) {
            float u, v0, v1, v2, v3;
            u = aqc - sv.x; v0 = ex2(-u * u);
            u = aqc - sv.y; v1 = ex2(-u * u);
            u = aqc - sv.z; v2 = ex2(-u * u);
            u = aqc - sv.w; v3 = ex2(-u * u);
            rowc += (v0 + v1) + (v2 + v3);
            aqc  = __shfl_sync(FULL, aqc,  (lane + 1) & 31);
            rowc = __shfl_sync(FULL, rowc, (lane + 1) & 31);
        }
        g_part[I * (RR * BB) + r * BB + I * 128 + tid] = rowc;
    }
}

// ---------------------------------------------------------------------------
// Stage 3 (fused, FINAL): blocks [0, QT*RR)     -> logsum of densities
//                         blocks [QT*RR, +GRB)  -> Gram fold + mean-correct +
//                                                  off-diag square-sum
// Each block fire-and-forget atomicAdd's its weighted partial into out[0]
// (zeroed by prep). total = (1/(B*R))*sum log(dens+eps) + sum_offdiag cov^2.
// ---------------------------------------------------------------------------
__global__ void reduce_kernel(float* __restrict__ out) {
    __shared__ float red[128];
    const int tid = threadIdx.x;   // 128

    if (blockIdx.x < QT * RR) {
        // ---------------- logsum half ----------------
        const int r  = blockIdx.x >> 4;
        const int qt = blockIdx.x & 15;
        const int q  = qt * 128 + tid;

        float s = 0.f;
        #pragma unroll
        for (int slot = 0; slot < TILES; ++slot)
            s += g_part[slot * (RR * BB) + r * BB + q];

        const float dens = s * g_dnorm[r];
        red[tid] = logf(dens + 1e-8f);
        __syncthreads();
        for (int o = 64; o > 0; o >>= 1) {
            if (tid < o) red[tid] += red[tid + o];
            __syncthreads();
        }
        if (tid == 0) atomicAdd(out, red[0] * (1.0f / (float)(BB * RR)));
    } else {
        // ---------------- Gram-reduce half ----------------
        const int gb = blockIdx.x - QT * RR;   // 0..GRB-1
        const int p  = gb * 128 + tid;         // cell in 64x64
        const int i  = p & (RR - 1);
        const int j  = p >> 6;

        float g = 0.f;
        #pragma unroll 16
        for (int b = 0; b < CB; ++b) g += g_gram[b * RR * RR + p];

        // centered Gram: sum((x_i - m_i)(x_j - m_j)) = raw - B*m_i*m_j
        g -= (float)BB * g_mean[i] * g_mean[j];

        float cs = 0.f;
        if (i != j) {
            const float c = g * (1.0f / (BB - 1));
            cs = c * c;
        }
        red[tid] = cs;
        __syncthreads();
        for (int o = 64; o > 0; o >>= 1) {
            if (tid < o) red[tid] += red[tid + o];
            __syncthreads();
        }
        if (tid == 0) atomicAdd(out, red[0]);
    }
}

// ---------------------------------------------------------------------------
extern "C" void kernel_launch(void* const* d_in, const int* in_sizes, int n_in,
                              void* d_out, int out_size) {
    const float* act = (const float*)d_in[0];
    float* out = (float*)d_out;
    (void)in_sizes; (void)n_in; (void)out_size;

    prep_kernel<<<CB, 256>>>(act, out);
    kde_sym_kernel<<<dim3(NPAIRS, RR), 128>>>();
    reduce_kernel<<<QT * RR + GRB, 128>>>(out);
}

// round 17
// speedup vs baseline: 1.0812x; 1.0812x over previous
#include <cuda_runtime.h>
#include <math.h>

// Problem constants
#define BB 2048     // batch (samples == queries)
#define RR 64       // receptors
#define TILES 16    // BB / 128
#define NPAIRS 136  // TILES*(TILES+1)/2
#define CB 128      // row-chunks for Gram/colsum partials
#define CROWS 16    // rows per chunk (CB*CROWS == BB)
#define GRB 32      // gram-fold blocks appended to the kde grid
#define KDE_BLOCKS (NPAIRS * RR)          // 8704
#define TOT_BLOCKS (KDE_BLOCKS + GRB)     // 8736

// -------- device scratch (static: no allocations allowed) --------
__device__ float g_act_t[RR * BB];       // column-major transpose of act (unscaled)
__device__ float g_k[RR];                // invh * sqrt(0.5*log2e) per receptor
__device__ float g_dnorm[RR];            // invh / (B * sqrt(2*pi))
__device__ float g_mean[RR];
__device__ float g_colsum[CB * RR];      // per-chunk column sums
__device__ float g_dens[RR * BB];        // accumulated densities (REDG targets)
__device__ unsigned int g_cnt[RR * TILES]; // per-(r,tile) arrival counters
__device__ float g_gram[CB * RR * RR];   // RAW (uncentered) Gram partials (2MB)

// Hardware exp2: single MUFU.EX2 (ftz on tiny results — harmless here).
__device__ __forceinline__ float ex2(float x) {
    float y;
    asm("ex2.approx.ftz.f32 %0, %1;" : "=f"(y) : "f"(x));
    return y;
}

// L2 load (bypass L1): epilogue reads of REDG-accumulated densities.
__device__ __forceinline__ float ldcg(const float* p) {
    float v;
    asm volatile("ld.global.cg.f32 %0, [%1];" : "=f"(v) : "l"(p));
    return v;
}

// ---------------------------------------------------------------------------
// Stage 1: per-chunk raw Gram (64x64) + per-chunk column sums + transposed
// copy of the chunk into column-major g_act_t (all from one coalesced tile).
// Block 0 zeroes out[0] (poisoned 0xAA by the harness).
// ---------------------------------------------------------------------------
__global__ void prep_kernel(const float* __restrict__ act, float* __restrict__ out) {
    __shared__ float ch[CROWS * RR];   // 16 x 64 raw rows (4KB)
    const int b   = blockIdx.x;        // 0..CB-1
    const int tid = threadIdx.x;       // 256

    if (b == 0 && tid == 0) out[0] = 0.f;

    reinterpret_cast<float4*>(ch)[tid] =
        reinterpret_cast<const float4*>(act + b * CROWS * RR)[tid];
    __syncthreads();

    // transposed write: i = r*16 + s  ->  g_act_t[r*BB + b*16 + s]
    #pragma unroll
    for (int i = tid; i < CROWS * RR; i += 256) {
        const int r = i >> 4;
        const int s = i & 15;
        g_act_t[r * BB + b * CROWS + s] = ch[s * RR + r];
    }

    // per-chunk column sums (threads 0..63)
    if (tid < RR) {
        float cs = 0.f;
        #pragma unroll
        for (int s = 0; s < CROWS; ++s) cs += ch[s * RR + tid];
        g_colsum[b * RR + tid] = cs;
    }

    const int ti = tid & 15;
    const int tj = tid >> 4;
    float acc[4][4];
    #pragma unroll
    for (int y = 0; y < 4; ++y)
        #pragma unroll
        for (int x = 0; x < 4; ++x) acc[y][x] = 0.f;

    const float4* __restrict__ s4 = reinterpret_cast<const float4*>(ch);
    #pragma unroll
    for (int s = 0; s < CROWS; ++s) {
        const float4 ai = s4[s * 16 + ti];
        const float4 aj = s4[s * 16 + tj];
        const float av[4] = { ai.x, ai.y, ai.z, ai.w };
        const float bv[4] = { aj.x, aj.y, aj.z, aj.w };
        #pragma unroll
        for (int y = 0; y < 4; ++y)
            #pragma unroll
            for (int x = 0; x < 4; ++x)
                acc[y][x] += av[x] * bv[y];
    }

    float* __restrict__ gp = g_gram + b * RR * RR;
    #pragma unroll
    for (int y = 0; y < 4; ++y)
        #pragma unroll
        for (int x = 0; x < 4; ++x)
            gp[(tj * 4 + y) * RR + (ti * 4 + x)] = acc[y][x];
}

// ---------------------------------------------------------------------------
// Stage 1b: finalize per-receptor stats (64 blocks — strided partial reads
// happen exactly once here) + zero the density accumulators and arrival
// counters for this launch (graph-replay safe: re-zeroed every call).
// var = (sumsq - B*mean^2)/(B-1): raw-moment form; validated rel_err ~e-6.
// ---------------------------------------------------------------------------
__global__ void finalize_kernel() {
    __shared__ float rs[CB], rq[CB];
    const int r = blockIdx.x;      // 0..RR-1
    const int t = threadIdx.x;     // 128 == CB

    // zero this receptor's density row (2048 floats) and counters (16)
    float4 z4 = make_float4(0.f, 0.f, 0.f, 0.f);
    float4* __restrict__ d4 = reinterpret_cast<float4*>(g_dens + r * BB);
    #pragma unroll
    for (int i = 0; i < 4; ++i) d4[i * CB + t] = z4;
    if (t < TILES) g_cnt[r * TILES + t] = 0u;

    rs[t] = g_colsum[t * RR + r];
    rq[t] = g_gram[t * RR * RR + r * RR + r];   // chunk diagonal = sum x^2
    __syncthreads();
    for (int o = 64; o > 0; o >>= 1) {
        if (t < o) { rs[t] += rs[t + o]; rq[t] += rq[t + o]; }
        __syncthreads();
    }
    if (t == 0) {
        const float mean = rs[0] * (1.0f / BB);
        const float ssc  = rq[0] - (float)BB * mean * mean;
        const float var  = ssc * (1.0f / (BB - 1));
        const float stdv = sqrtf(var);
        // BANDWIDTH_FACTOR * std * B^(-0.2);  2048^(-0.2) = 0.21763764
        const float h    = fmaxf(1.06f * stdv * 0.21763764f, 1e-4f);
        const float invh = 1.0f / h;
        // sqrt(0.5 * log2(e)) so exp(-0.5*u^2) == 2^{-(u')^2}
        g_k[r]     = invh * 0.84932184f;
        g_dnorm[r] = invh * (1.0f / (2048.0f * 2.5066282746310002f));
        g_mean[r]  = mean;
    }
}

// ---------------------------------------------------------------------------
// Stage 2 (FINAL): symmetric KDE + in-kernel logsum epilogue + Gram fold.
// Blocks [0, KDE_BLOCKS): pair-tile KDE. Contributions go straight into
//   g_dens via fire-and-forget atomicAdd. Each (r,tile) has exactly 16
//   contributing blocks; a per-(r,tile) counter (zeroed in finalize) lets
//   the 16th arrival fence, re-read the 128 densities via ld.cg, compute
//   the log-sum, and REDG it into out. With ~59 blocks queued per SM these
//   epilogues hide entirely except the very last tile.
// Blocks [KDE_BLOCKS, TOT_BLOCKS): Gram fold + mean-correct + off-diag
//   square-sum -> REDG into out (inputs complete before this launch).
// No spin-waits anywhere; every block either exits or does bounded work.
// ---------------------------------------------------------------------------
__global__ void kde_kernel(float* __restrict__ out) {
    __shared__ float shc[4][128];
    __shared__ int sEpiI, sEpiJ;
    const int tid = threadIdx.x;   // 128

    if (blockIdx.x >= KDE_BLOCKS) {
        // ---------------- Gram-fold half ----------------
        const int gb = blockIdx.x - KDE_BLOCKS;   // 0..GRB-1
        const int p  = gb * 128 + tid;            // cell in 64x64
        const int i  = p & (RR - 1);
        const int j  = p >> 6;

        float g = 0.f;
        #pragma unroll 16
        for (int b = 0; b < CB; ++b) g += g_gram[b * RR * RR + p];

        g -= (float)BB * g_mean[i] * g_mean[j];   // centered Gram

        float cs = 0.f;
        if (i != j) {
            const float c = g * (1.0f / (BB - 1));
            cs = c * c;
        }
        shc[0][tid] = cs;
        __syncthreads();
        for (int o = 64; o > 0; o >>= 1) {
            if (tid < o) shc[0][tid] += shc[0][tid + o];
            __syncthreads();
        }
        if (tid == 0) atomicAdd(out, shc[0][0]);
        return;
    }

    // ---------------- KDE half ----------------
    const int r = blockIdx.x / NPAIRS;
    int I = 0, rem = blockIdx.x % NPAIRS;   // pair index -> (I, J), I <= J
    while (rem >= TILES - I) { rem -= TILES - I; ++I; }
    const int J = I + rem;

    const int lane = tid & 31;
    const int w    = tid >> 5;

    const float kk = g_k[r];
    const float* __restrict__ col = g_act_t + r * BB;
    float* __restrict__ dens = g_dens + r * BB;

    float4 sv = reinterpret_cast<const float4*>(col + J * 128)[lane];
    sv.x *= kk; sv.y *= kk; sv.z *= kk; sv.w *= kk;
    float aqc  = col[I * 128 + tid] * kk;
    float rowc = 0.f;
    float4 ca  = make_float4(0.f, 0.f, 0.f, 0.f);

    const unsigned FULL = 0xFFFFFFFFu;

    if (I != J) {
        #pragma unroll 8
        for (int m = 0; m < 32; ++m) {
            float u, v0, v1, v2, v3;
            u = aqc - sv.x; v0 = ex2(-u * u);
            u = aqc - sv.y; v1 = ex2(-u * u);
            u = aqc - sv.z; v2 = ex2(-u * u);
            u = aqc - sv.w; v3 = ex2(-u * u);
            ca.x += v0; ca.y += v1; ca.z += v2; ca.w += v3;
            rowc += (v0 + v1) + (v2 + v3);
            aqc  = __shfl_sync(FULL, aqc,  (lane + 1) & 31);
            rowc = __shfl_sync(FULL, rowc, (lane + 1) & 31);
        }

        reinterpret_cast<float4*>(shc[w])[lane] = ca;
        __syncthreads();
        const float ct = shc[0][tid] + shc[1][tid] + shc[2][tid] + shc[3][tid];

        atomicAdd(&dens[J * 128 + tid], ct);    // tile-J densities
        atomicAdd(&dens[I * 128 + tid], rowc);  // tile-I densities
    } else {
        #pragma unroll 8
        for (int m = 0; m < 32; ++m) {
            float u, v0, v1, v2, v3;
            u = aqc - sv.x; v0 = ex2(-u * u);
            u = aqc - sv.y; v1 = ex2(-u * u);
            u = aqc - sv.z; v2 = ex2(-u * u);
            u = aqc - sv.w; v3 = ex2(-u * u);
            rowc += (v0 + v1) + (v2 + v3);
            aqc  = __shfl_sync(FULL, aqc,  (lane + 1) & 31);
            rowc = __shfl_sync(FULL, rowc, (lane + 1) & 31);
        }
        atomicAdd(&dens[I * 128 + tid], rowc);
    }

    // ---- arrival tickets: 16th contributor per (r,tile) runs the logsum ----
    __threadfence();                 // release this block's density adds
    __syncthreads();
    if (tid == 0) {
        const unsigned tj = atomicAdd(&g_cnt[r * TILES + J], 1u);
        sEpiJ = (tj == 15u);
        if (I != J) {
            const unsigned ti2 = atomicAdd(&g_cnt[r * TILES + I], 1u);
            sEpiI = (ti2 == 15u);
        } else {
            sEpiI = 0;
        }
    }
    __syncthreads();
    if (!sEpiI && !sEpiJ) return;

    __threadfence();                 // acquire: see all 16 contributions
    const float dn = g_dnorm[r];

    #pragma unroll 1
    for (int e = 0; e < 2; ++e) {
        const int flag = (e == 0) ? sEpiJ : sEpiI;
        if (!flag) continue;
        const int T = (e == 0) ? J : I;
        const float d  = ldcg(&dens[T * 128 + tid]) * dn;
        shc[0][tid] = logf(d + 1e-8f);
        __syncthreads();
        for (int o = 64; o > 0; o >>= 1) {
            if (tid < o) shc[0][tid] += shc[0][tid + o];
            __syncthreads();
        }
        if (tid == 0) atomicAdd(out, shc[0][0] * (1.0f / (float)(BB * RR)));
        __syncthreads();
    }
}

// ---------------------------------------------------------------------------
extern "C" void kernel_launch(void* const* d_in, const int* in_sizes, int n_in,
                              void* d_out, int out_size) {
    const float* act = (const float*)d_in[0];
    float* out = (float*)d_out;
    (void)in_sizes; (void)n_in; (void)out_size;

    prep_kernel<<<CB, 256>>>(act, out);
    finalize_kernel<<<RR, CB>>>();
    kde_kernel<<<TOT_BLOCKS, 128>>>(out);
}